// round 14
// baseline (speedup 1.0000x reference)
#include <cuda_runtime.h>
#include <cuda_bf16.h>
#include <cstdint>

#define B_    32
#define CIN_  64
#define COUT_ 64
#define ADIM_ 64
#define H_    128
#define W_    128
#define KVOL_ (COUT_*CIN_*9)

// tcgen05 only exists under arch-specific (sm_103a/sm_100a) compilation.
#if defined(__CUDA_ARCH_FEAT_SM103_ALL) || defined(__CUDA_ARCH_FEAT_SM100_ALL) || \
    (defined(__CUDA_ARCH_SPECIFIC__))
#define HAS_TCGEN05 1
#else
#define HAS_TCGEN05 0
#endif

// ---------------- device scratch ----------------
__device__ float g_pooled[B_ * CIN_];
__device__ float g_hid[B_ * ADIM_];
__device__ float g_wadapt[B_ * KVOL_];   // fp32 weights (fallback path)
// pre-swizzled bf16 weight tiles: [b][dy][hi/lo] x 24576 bytes (64 x 192, blocked-atom SW128)
__device__ unsigned char g_wB[B_ * 3 * 2 * 24576];

// ---------------- helpers ----------------
__device__ __forceinline__ uint32_t smem_u32(const void* p) {
    uint32_t a;
    asm("{ .reg .u64 t; cvta.to.shared.u64 t, %1; cvt.u32.u64 %0, t; }" : "=r"(a) : "l"(p));
    return a;
}
__device__ __forceinline__ uint32_t swzB(int n, int k) {   // 64 rows x 192 k
    uint32_t byte = (uint32_t)(k >> 6) * 8192u + ((uint32_t)(n >> 3) << 10) +
                    ((uint32_t)(n & 7) << 7) + ((uint32_t)(k & 63) << 1);
    return byte ^ ((byte >> 3) & 0x70u);
}

#if HAS_TCGEN05
__device__ __forceinline__ uint32_t elect_one() {
    uint32_t pred;
    asm volatile("{\n\t.reg .pred p;\n\telect.sync _|p, 0xFFFFFFFF;\n\t"
                 "selp.b32 %0, 1, 0, p;\n\t}" : "=r"(pred));
    return pred;
}
#define MBAR_INIT(a, c) asm volatile("mbarrier.init.shared.b64 [%0], %1;" :: "r"(a), "r"(c) : "memory")
#define MBAR_ARRIVE(a)  asm volatile("mbarrier.arrive.shared.b64 _, [%0];" :: "r"(a) : "memory")
#define MBAR_WAIT(a, ph) do {                                                                   \
    uint32_t _m = (a), _p = (ph), _d;                                                           \
    asm volatile("{\n\t.reg .pred p;\n\t"                                                       \
        "mbarrier.try_wait.parity.acquire.cta.shared::cta.b64 p, [%1], %2;\n\t"                 \
        "selp.b32 %0, 1, 0, p;\n\t}" : "=r"(_d) : "r"(_m), "r"(_p) : "memory");                 \
    if (!_d) {                                                                                  \
        asm volatile("{\n\t.reg .pred P1;\n\t"                                                  \
            "WL_%=:\n\t"                                                                        \
            "mbarrier.try_wait.parity.acquire.cta.shared::cta.b64 P1, [%0], %1, 0x989680;\n\t"  \
            "@P1 bra.uni WD_%=;\n\t"                                                            \
            "bra.uni WL_%=;\n\t"                                                                \
            "WD_%=:\n\t}" :: "r"(_m), "r"(_p) : "memory");                                      \
    }                                                                                           \
} while (0)
#define BAR1_512() asm volatile("bar.sync 1, 512;" ::: "memory")
#define TC_ALLOC(sa, n)   asm volatile("tcgen05.alloc.cta_group::1.sync.aligned.shared::cta.b32 [%0], %1;" :: "r"(sa), "r"(n) : "memory")
#define TC_DEALLOC(t, n)  asm volatile("tcgen05.dealloc.cta_group::1.sync.aligned.b32 %0, %1;" :: "r"(t), "r"(n))
#define TC_COMMIT(mb)     asm volatile("tcgen05.commit.cta_group::1.mbarrier::arrive::one.shared::cluster.b64 [%0];" :: "r"(mb) : "memory")
#define TC_FENCE_AFTER()  asm volatile("tcgen05.fence::after_thread_sync;" ::: "memory")
#define TC_FENCE_BEFORE() asm volatile("tcgen05.fence::before_thread_sync;" ::: "memory")
#define TC_WAIT_LD()      asm volatile("tcgen05.wait::ld.sync.aligned;" ::: "memory")
#define TC_WAIT_ST()      asm volatile("tcgen05.wait::st.sync.aligned;" ::: "memory")
#define FENCE_ASYNC()     asm volatile("fence.proxy.async.shared::cta;" ::: "memory")

#define TC_LD_X32(r, ta) \
    asm volatile("tcgen05.ld.sync.aligned.32x32b.x32.b32 " \
        "{%0, %1, %2, %3, %4, %5, %6, %7, %8, %9, %10, %11, %12, %13, %14, %15, " \
        "%16, %17, %18, %19, %20, %21, %22, %23, %24, %25, %26, %27, %28, %29, %30, %31}, [%32];" \
        : "=r"((r)[0]),  "=r"((r)[1]),  "=r"((r)[2]),  "=r"((r)[3]), \
          "=r"((r)[4]),  "=r"((r)[5]),  "=r"((r)[6]),  "=r"((r)[7]), \
          "=r"((r)[8]),  "=r"((r)[9]),  "=r"((r)[10]), "=r"((r)[11]), \
          "=r"((r)[12]), "=r"((r)[13]), "=r"((r)[14]), "=r"((r)[15]), \
          "=r"((r)[16]), "=r"((r)[17]), "=r"((r)[18]), "=r"((r)[19]), \
          "=r"((r)[20]), "=r"((r)[21]), "=r"((r)[22]), "=r"((r)[23]), \
          "=r"((r)[24]), "=r"((r)[25]), "=r"((r)[26]), "=r"((r)[27]), \
          "=r"((r)[28]), "=r"((r)[29]), "=r"((r)[30]), "=r"((r)[31]) \
        : "r"(ta))

#define TC_ST_X8(ta, r) \
    asm volatile("tcgen05.st.sync.aligned.32x32b.x8.b32 [%0], " \
        "{%1, %2, %3, %4, %5, %6, %7, %8};" \
        :: "r"(ta), \
           "r"((r)[0]), "r"((r)[1]), "r"((r)[2]), "r"((r)[3]), \
           "r"((r)[4]), "r"((r)[5]), "r"((r)[6]), "r"((r)[7]) \
        : "memory")

// TS-mode f16 MMA: A in TMEM, B in smem (pattern: test_mma.cu / test_mma_iter.cu)
__device__ __forceinline__ void mma_f16_ts(uint32_t d, uint32_t a_tmem, uint64_t bd,
                                           uint32_t idesc, uint32_t en) {
    asm volatile("{\n\t.reg .pred p;\n\tsetp.ne.u32 p, %5, 0;\n\t"
        "tcgen05.mma.cta_group::1.kind::f16 [%0], [%1], %2, %3, {%4, %4, %4, %4}, p;\n\t}"
        :: "r"(d), "r"(a_tmem), "l"(bd), "r"(idesc), "r"(0u), "r"(en) : "memory");
}
__device__ __forceinline__ uint64_t make_desc(uint32_t addr) {
    uint64_t d = (uint64_t(2) << 61) | (uint64_t(1) << 46) |
                 (uint64_t(64) << 32) | (uint64_t(1) << 16);
    return d | ((uint64_t)(addr >> 4) & 0x3FFF);
}
// idesc: F32 accum(bit4), BF16 a(bit7), BF16 b(bit10), N=64 (8<<17), M=128 (8<<24)
#define IDESC_ 0x08100490u
#endif  // HAS_TCGEN05

// ============================================================
// Kernel 1: global average pool
// ============================================================
__global__ void pool_kernel(const float* __restrict__ x) {
    int plane = blockIdx.x;
    const float4* p = (const float4*)(x + ((size_t)plane << 14));
    float s = 0.f;
    for (int i = threadIdx.x; i < (H_ * W_ / 4); i += 256) {
        float4 v = p[i];
        s += (v.x + v.y) + (v.z + v.w);
    }
#pragma unroll
    for (int o = 16; o; o >>= 1) s += __shfl_xor_sync(0xffffffffu, s, o);
    __shared__ float red[8];
    if ((threadIdx.x & 31) == 0) red[threadIdx.x >> 5] = s;
    __syncthreads();
    if (threadIdx.x == 0) {
        float t = 0.f;
#pragma unroll
        for (int i = 0; i < 8; i++) t += red[i];
        g_pooled[plane] = t * (1.f / (H_ * W_));
    }
}

// ============================================================
// Kernel 2: h = relu(pooled @ w1 + b1), one block per sample
// ============================================================
__global__ void mlp1_kernel(const float* __restrict__ w1, const float* __restrict__ b1) {
    int b = blockIdx.x;
    int a = threadIdx.x;     // 64 threads
    __shared__ float sp[CIN_];
    sp[a] = g_pooled[b * CIN_ + a];
    __syncthreads();
    float acc = b1[a];
#pragma unroll 16
    for (int k = 0; k < CIN_; k++) acc += sp[k] * w1[k * ADIM_ + a];
    g_hid[b * ADIM_ + a] = fmaxf(acc, 0.f);
}

// ============================================================
// Kernel 3: adapted weights -> fp32 (fallback) + bf16 hi/lo swizzled tiles
// ============================================================
__global__ void adapt_kernel(const float* __restrict__ base_w,
                             const float* __restrict__ w2,
                             const float* __restrict__ b2,
                             const float* __restrict__ scale_p) {
    __shared__ float sh[B_][ADIM_ + 1];
    __shared__ float sw2[ADIM_][8];
    int col0 = blockIdx.x * 8;
    for (int i = threadIdx.x; i < B_ * ADIM_; i += 256)
        sh[i >> 6][i & 63] = g_hid[i];
    for (int i = threadIdx.x; i < ADIM_ * 8; i += 256)
        sw2[i >> 3][i & 7] = w2[(size_t)(i >> 3) * KVOL_ + col0 + (i & 7)];
    __syncthreads();
    int j = threadIdx.x >> 5;
    int b = threadIdx.x & 31;
    int col = col0 + j;
    float acc = b2[col];
#pragma unroll
    for (int a = 0; a < ADIM_; a++) acc += sh[b][a] * sw2[a][j];
    float w = base_w[col] + scale_p[0] * tanhf(acc);
    g_wadapt[(size_t)b * KVOL_ + col] = w;
    // col = ((n*64+ci)*3+dy)*3+dx
    int t1 = col / 3, dx = col - 3 * t1;
    int t2 = t1 / 3, dy = t1 - 3 * t2;
    int ci = t2 & 63, n = t2 >> 6;
    __nv_bfloat16 hi = __float2bfloat16(w);
    __nv_bfloat16 lo = __float2bfloat16(w - __bfloat162float(hi));
    uint32_t off = swzB(n, dx * 64 + ci);
    size_t base = (size_t)((b * 3 + dy) * 2) * 24576;
    *(__nv_bfloat16*)(g_wB + base + off) = hi;
    *(__nv_bfloat16*)(g_wB + base + 24576 + off) = lo;
}

// ============================================================
// Kernel 4: tensor-core implicit conv (sm_103a), 544 threads
//   Warp-specialized + DOUBLE-BUFFERED A in TMEM.
//   CTA = (b, 2 output rows). TMEM: D 128 + 2 x (Ah 96 + Al 96) = 512.
//   FIX vs R13: epilogue subpartition mapping is wid&3 (hardware-
//   implied by tcgen05.ld), row/half come from wid>>2.
// ============================================================
#define MB_MDONE0   8u
#define MB_MDONE1   16u
#define MB_AREADY   24u
#define SM_SCRATCH  1024u                 // uint32 [130][65] = 33800B
#define SCRATCH_END (1024u + 33800u)
#define T_B   0u                          // 3 dy x (hi 24576 + lo 24576)
#define T_SZ  147456u
#define SM_TOTAL (SCRATCH_END + 1024u + T_SZ)   // ~183.3KB -> 1 CTA/SM

#define TM_D   0u        // D: 2 tiles x 64 cols = 128
#define TM_A0  128u      // buf0: Ah @128, Al @224
#define TM_A1  320u      // buf1: Ah @320, Al @416

#define NTHREADS 544     // 16 builder warps + 1 MMA warp
#define NROWS    4       // input rows h0-1 .. h0+2

__global__ void __launch_bounds__(NTHREADS, 1)
conv_tc_kernel(const float* __restrict__ x,
               const float* __restrict__ base_b,
               float* __restrict__ y) {
#if HAS_TCGEN05
    extern __shared__ unsigned char sm[];
    __shared__ float sbb[COUT_];
    const uint32_t sbase = smem_u32(sm);
    uint32_t* scratch = (uint32_t*)(sm + SM_SCRATCH);

    const uint32_t tbase = (sbase + SCRATCH_END + 1023u) & ~1023u;
    unsigned char* tptr = sm + (tbase - sbase);

    const int tid = threadIdx.x;
    const int wid = tid >> 5;
    const int lid = tid & 31;
    const int h0 = blockIdx.x * 2;
    const int b  = blockIdx.y;
    const float* xb = x + ((size_t)b << 20);

    if (tid == 0) {
        MBAR_INIT(sbase + MB_MDONE0, 1);
        MBAR_INIT(sbase + MB_MDONE1, 1);
        MBAR_INIT(sbase + MB_AREADY, 1);
    }
    if (wid == 0) TC_ALLOC(sbase, 512);
    if (tid < COUT_) sbb[tid] = base_b[tid];
    if (tid < 64) { scratch[tid] = 0u; scratch[129 * 65 + tid] = 0u; }  // halo rows 0,129
    __syncthreads();
    uint32_t tmem;
    asm volatile("ld.shared.b32 %0, [%1];" : "=r"(tmem) : "r"(sbase));

    const uint64_t dB = make_desc(tbase + T_B);

    if (wid == 16) {
        // ================= MMA issue warp =================
        for (int ri = 0; ri < NROWS; ri++) {
            MBAR_WAIT(sbase + MB_AREADY, ri & 1);
            FENCE_ASYNC();
            TC_FENCE_AFTER();
            if (elect_one()) {
                uint32_t aBase = tmem + ((ri & 1) ? TM_A1 : TM_A0);
                int dylo = ri - 1 > 0 ? ri - 1 : 0;
                int dyhi = ri < 2 ? ri : 2;
                for (int dy = dylo; dy <= dyhi; dy++) {
                    int hh = ri - dy;                    // 0 or 1
                    uint32_t d = tmem + TM_D + hh * 64;
                    uint64_t bH = dB + (uint64_t)(dy * 3072);
                    uint64_t bL = bH + 1536;
#pragma unroll
                    for (int s = 0; s < 12; s++) {
                        uint64_t bo = (uint64_t)((s >> 2) * 512 + (s & 3) * 2);
                        mma_f16_ts(d, aBase + s * 8, bH + bo, IDESC_,
                                   !(dy == 0 && s == 0));
                    }
#pragma unroll
                    for (int s = 0; s < 12; s++) {
                        uint64_t bo = (uint64_t)((s >> 2) * 512 + (s & 3) * 2);
                        mma_f16_ts(d, aBase + 96 + s * 8, bH + bo, IDESC_, 1u);
                    }
#pragma unroll
                    for (int s = 0; s < 12; s++) {
                        uint64_t bo = (uint64_t)((s >> 2) * 512 + (s & 3) * 2);
                        mma_f16_ts(d, aBase + s * 8, bL + bo, IDESC_, 1u);
                    }
                }
                TC_COMMIT(sbase + ((ri & 1) ? MB_MDONE1 : MB_MDONE0));
            }
        }
    } else {
        // ================= 16 builder warps =================
        // prologue: stage ALL B tiles (3 dy x hi/lo, contiguous in g_wB)
        {
            const uint4* src = (const uint4*)(g_wB + (size_t)(b * 3) * 2 * 24576);
            uint4* dst = (uint4*)(tptr + T_B);
            for (int i = tid; i < (int)(T_SZ / 16); i += 512) dst[i] = src[i];
        }

        const int pf_w4 = tid & 31;
        const int ci_base = tid >> 5;        // ci = it*16 + ci_base (0..15)
        const int am = tid & 127;
        const int awg = tid >> 7;            // 0..3
        const uint32_t warp_off = (uint32_t)((tid & 127) >> 5) << 21;

        float4 v[4];
        // prologue: load input row for ri=0 (row = h0-1; clamp, zero-fill)
        {
            int r = h0 - 1;
            bool valid = r >= 0;
            int rc = valid ? r : 0;
            const float4* xr4 = (const float4*)(xb + ((size_t)rc << 7));
#pragma unroll
            for (int it = 0; it < 4; it++) {
                float4 t = xr4[((size_t)(it * 16 + ci_base) << 12) + pf_w4];
                v[it] = valid ? t : make_float4(0.f, 0.f, 0.f, 0.f);
            }
        }

        for (int ri = 0; ri < NROWS; ri++) {
            // stage scratch(ri) from registers
#pragma unroll
            for (int it = 0; it < 4; it++) {
                float vv[4] = {v[it].x, v[it].y, v[it].z, v[it].w};
                int ci = it * 16 + ci_base;
                int wbase = (pf_w4 << 2) + 1;
#pragma unroll
                for (int q = 0; q < 4; q++) {
                    __nv_bfloat16 hi = __float2bfloat16(vv[q]);
                    __nv_bfloat16 lo = __float2bfloat16(vv[q] - __bfloat162float(hi));
                    scratch[(wbase + q) * 65 + ci] =
                        (uint32_t)__bfloat16_as_ushort(hi) |
                        ((uint32_t)__bfloat16_as_ushort(lo) << 16);
                }
            }
            BAR1_512();                      // scratch(ri) + (ri==0: B copy) visible

            // hoisted LDG: input row for ri+1  (row = h0 + ri)
            if (ri + 1 < NROWS) {
                int r = h0 + ri;
                bool valid = r < H_;
                int rc = valid ? r : (H_ - 1);
                const float4* xr4 = (const float4*)(xb + ((size_t)rc << 7));
#pragma unroll
                for (int it = 0; it < 4; it++) {
                    float4 t = xr4[((size_t)(it * 16 + ci_base) << 12) + pf_w4];
                    v[it] = valid ? t : make_float4(0.f, 0.f, 0.f, 0.f);
                }
            }

            // wait for the MMAs that used THIS buffer two rows ago
            if (ri >= 2)
                MBAR_WAIT(sbase + ((ri & 1) ? MB_MDONE1 : MB_MDONE0), 0);

            // A build into TMEM buffer ri&1
            {
                uint32_t aBase = tmem + ((ri & 1) ? TM_A1 : TM_A0) + warp_off;
#pragma unroll
                for (int chunk = 0; chunk < 3; chunk++) {
                    int c0 = awg * 24 + chunk * 8;
                    uint32_t hi[8], lo[8];
#pragma unroll
                    for (int j = 0; j < 8; j++) {
                        int c = c0 + j;
                        int kk2 = 2 * c;
                        int dx = kk2 >> 6;
                        int ci = kk2 & 63;
                        const uint32_t* s2 = &scratch[(am + dx) * 65 + ci];
                        uint32_t w0 = s2[0], w1 = s2[1];
                        hi[j] = __byte_perm(w0, w1, 0x5410);
                        lo[j] = __byte_perm(w0, w1, 0x7632);
                    }
                    TC_ST_X8(aBase + c0, hi);
                    TC_ST_X8(aBase + 96 + c0, lo);
                }
            }
            TC_WAIT_ST();
            TC_FENCE_BEFORE();
            BAR1_512();                      // all of A(ri) in TMEM
            if (tid == 0) MBAR_ARRIVE(sbase + MB_AREADY);
        }

        // final completion: both buffers' second commits (rows 2 and 3)
        MBAR_WAIT(sbase + MB_MDONE0, 1);
        MBAR_WAIT(sbase + MB_MDONE1, 1);
        TC_FENCE_AFTER();

        // epilogue: warp w: subpartition = w&3 (HW-implied by tcgen05.ld),
        //           hh = (w>>2)&1, half = w>>3
        {
            int sub = wid & 3, hh = (wid >> 2) & 1, half = wid >> 3;
            int m = sub * 32 + lid;
            int h = h0 + hh;
            float* yr = y + ((size_t)b << 20) + ((size_t)h << 7) + m;
            uint32_t r0[32];
            TC_LD_X32(r0, tmem + TM_D + hh * 64 + half * 32);
            TC_WAIT_LD();
#pragma unroll
            for (int c = 0; c < 32; c++) {
                int co = half * 32 + c;
                yr[(size_t)co << 14] = __uint_as_float(r0[c]) + sbb[co];
            }
        }
        TC_FENCE_BEFORE();
    }

    __syncthreads();
    if (wid == 0) TC_DEALLOC(tmem, 512);

#else  // -------- generic-PTX fallback: correct scalar conv --------
    const int tid = threadIdx.x;
    const int h0 = blockIdx.x * 2;
    const int b  = blockIdx.y;
    const float* xb = x + ((size_t)b << 20);
    const float* wgt_b = g_wadapt + (size_t)b * KVOL_;
    for (int idx = tid; idx < 2 * 128 * 64; idx += NTHREADS) {
        int w = idx & 127;
        int rest = idx >> 7;
        int co = rest & 63;
        int hh = rest >> 6;
        int h = h0 + hh;
        float acc = base_b[co];
        const float* wgt = wgt_b + co * 576;
        for (int ci = 0; ci < CIN_; ci++) {
            const float* xp = xb + ((size_t)ci << 14);
            const float* wp = wgt + ci * 9;
            for (int ky = 0; ky < 3; ky++) {
                int ih = h + ky - 1;
                if ((unsigned)ih >= (unsigned)H_) continue;
                for (int kx = 0; kx < 3; kx++) {
                    int iw = w + kx - 1;
                    if ((unsigned)iw >= (unsigned)W_) continue;
                    acc += xp[(ih << 7) + iw] * wp[ky * 3 + kx];
                }
            }
        }
        y[((size_t)b << 20) + ((size_t)co << 14) + ((size_t)h << 7) + w] = acc;
    }
#endif
}

// ============================================================
extern "C" void kernel_launch(void* const* d_in, const int* in_sizes, int n_in,
                              void* d_out, int out_size) {
    const float* x      = (const float*)d_in[0];
    const float* base_w = (const float*)d_in[1];
    const float* base_b = (const float*)d_in[2];
    const float* w1     = (const float*)d_in[3];
    const float* b1     = (const float*)d_in[4];
    const float* w2     = (const float*)d_in[5];
    const float* b2     = (const float*)d_in[6];
    const float* scale  = (const float*)d_in[7];
    float* y = (float*)d_out;

    cudaFuncSetAttribute(conv_tc_kernel,
                         cudaFuncAttributeMaxDynamicSharedMemorySize, SM_TOTAL);

    pool_kernel<<<B_ * CIN_, 256>>>(x);
    mlp1_kernel<<<B_, 64>>>(w1, b1);
    adapt_kernel<<<KVOL_ / 8, 256>>>(base_w, w2, b2, scale);
    conv_tc_kernel<<<dim3(H_ / 2, B_), NTHREADS, SM_TOTAL>>>(x, base_b, y);
}

// round 15
// speedup vs baseline: 1.2226x; 1.2226x over previous
#include <cuda_runtime.h>
#include <cuda_bf16.h>
#include <cstdint>

#define B_    32
#define CIN_  64
#define COUT_ 64
#define ADIM_ 64
#define H_    128
#define W_    128
#define KVOL_ (COUT_*CIN_*9)

// tcgen05 only exists under arch-specific (sm_103a/sm_100a) compilation.
#if defined(__CUDA_ARCH_FEAT_SM103_ALL) || defined(__CUDA_ARCH_FEAT_SM100_ALL) || \
    (defined(__CUDA_ARCH_SPECIFIC__))
#define HAS_TCGEN05 1
#else
#define HAS_TCGEN05 0
#endif

// ---------------- device scratch ----------------
__device__ float g_pooled[B_ * CIN_];
__device__ float g_hid[B_ * ADIM_];
__device__ float g_wadapt[B_ * KVOL_];   // fp32 weights (fallback path)
// pre-swizzled bf16 weight tiles: [b][dy][hi/lo] x 24576 bytes (64 x 192, blocked-atom SW128)
__device__ unsigned char g_wB[B_ * 3 * 2 * 24576];

// ---------------- helpers ----------------
__device__ __forceinline__ uint32_t smem_u32(const void* p) {
    uint32_t a;
    asm("{ .reg .u64 t; cvta.to.shared.u64 t, %1; cvt.u32.u64 %0, t; }" : "=r"(a) : "l"(p));
    return a;
}
__device__ __forceinline__ uint32_t swzB(int n, int k) {   // 64 rows x 192 k
    uint32_t byte = (uint32_t)(k >> 6) * 8192u + ((uint32_t)(n >> 3) << 10) +
                    ((uint32_t)(n & 7) << 7) + ((uint32_t)(k & 63) << 1);
    return byte ^ ((byte >> 3) & 0x70u);
}

#if HAS_TCGEN05
__device__ __forceinline__ uint32_t elect_one() {
    uint32_t pred;
    asm volatile("{\n\t.reg .pred p;\n\telect.sync _|p, 0xFFFFFFFF;\n\t"
                 "selp.b32 %0, 1, 0, p;\n\t}" : "=r"(pred));
    return pred;
}
#define MBAR_INIT(a, c) asm volatile("mbarrier.init.shared.b64 [%0], %1;" :: "r"(a), "r"(c) : "memory")
#define MBAR_ARRIVE(a)  asm volatile("mbarrier.arrive.shared.b64 _, [%0];" :: "r"(a) : "memory")
#define MBAR_WAIT(a, ph) do {                                                                   \
    uint32_t _m = (a), _p = (ph), _d;                                                           \
    asm volatile("{\n\t.reg .pred p;\n\t"                                                       \
        "mbarrier.try_wait.parity.acquire.cta.shared::cta.b64 p, [%1], %2;\n\t"                 \
        "selp.b32 %0, 1, 0, p;\n\t}" : "=r"(_d) : "r"(_m), "r"(_p) : "memory");                 \
    if (!_d) {                                                                                  \
        asm volatile("{\n\t.reg .pred P1;\n\t"                                                  \
            "WL_%=:\n\t"                                                                        \
            "mbarrier.try_wait.parity.acquire.cta.shared::cta.b64 P1, [%0], %1, 0x989680;\n\t"  \
            "@P1 bra.uni WD_%=;\n\t"                                                            \
            "bra.uni WL_%=;\n\t"                                                                \
            "WD_%=:\n\t}" :: "r"(_m), "r"(_p) : "memory");                                      \
    }                                                                                           \
} while (0)
#define BAR1_512() asm volatile("bar.sync 1, 512;" ::: "memory")
#define TC_ALLOC(sa, n)   asm volatile("tcgen05.alloc.cta_group::1.sync.aligned.shared::cta.b32 [%0], %1;" :: "r"(sa), "r"(n) : "memory")
#define TC_DEALLOC(t, n)  asm volatile("tcgen05.dealloc.cta_group::1.sync.aligned.b32 %0, %1;" :: "r"(t), "r"(n))
#define TC_COMMIT(mb)     asm volatile("tcgen05.commit.cta_group::1.mbarrier::arrive::one.shared::cluster.b64 [%0];" :: "r"(mb) : "memory")
#define TC_FENCE_AFTER()  asm volatile("tcgen05.fence::after_thread_sync;" ::: "memory")
#define TC_FENCE_BEFORE() asm volatile("tcgen05.fence::before_thread_sync;" ::: "memory")
#define TC_WAIT_LD()      asm volatile("tcgen05.wait::ld.sync.aligned;" ::: "memory")
#define TC_WAIT_ST()      asm volatile("tcgen05.wait::st.sync.aligned;" ::: "memory")
#define FENCE_ASYNC()     asm volatile("fence.proxy.async.shared::cta;" ::: "memory")

#define TC_LD_X32(r, ta) \
    asm volatile("tcgen05.ld.sync.aligned.32x32b.x32.b32 " \
        "{%0, %1, %2, %3, %4, %5, %6, %7, %8, %9, %10, %11, %12, %13, %14, %15, " \
        "%16, %17, %18, %19, %20, %21, %22, %23, %24, %25, %26, %27, %28, %29, %30, %31}, [%32];" \
        : "=r"((r)[0]),  "=r"((r)[1]),  "=r"((r)[2]),  "=r"((r)[3]), \
          "=r"((r)[4]),  "=r"((r)[5]),  "=r"((r)[6]),  "=r"((r)[7]), \
          "=r"((r)[8]),  "=r"((r)[9]),  "=r"((r)[10]), "=r"((r)[11]), \
          "=r"((r)[12]), "=r"((r)[13]), "=r"((r)[14]), "=r"((r)[15]), \
          "=r"((r)[16]), "=r"((r)[17]), "=r"((r)[18]), "=r"((r)[19]), \
          "=r"((r)[20]), "=r"((r)[21]), "=r"((r)[22]), "=r"((r)[23]), \
          "=r"((r)[24]), "=r"((r)[25]), "=r"((r)[26]), "=r"((r)[27]), \
          "=r"((r)[28]), "=r"((r)[29]), "=r"((r)[30]), "=r"((r)[31]) \
        : "r"(ta))

#define TC_ST_X8(ta, r) \
    asm volatile("tcgen05.st.sync.aligned.32x32b.x8.b32 [%0], " \
        "{%1, %2, %3, %4, %5, %6, %7, %8};" \
        :: "r"(ta), \
           "r"((r)[0]), "r"((r)[1]), "r"((r)[2]), "r"((r)[3]), \
           "r"((r)[4]), "r"((r)[5]), "r"((r)[6]), "r"((r)[7]) \
        : "memory")

// TS-mode f16 MMA: A in TMEM, B in smem (pattern: test_mma.cu / test_mma_iter.cu)
__device__ __forceinline__ void mma_f16_ts(uint32_t d, uint32_t a_tmem, uint64_t bd,
                                           uint32_t idesc, uint32_t en) {
    asm volatile("{\n\t.reg .pred p;\n\tsetp.ne.u32 p, %5, 0;\n\t"
        "tcgen05.mma.cta_group::1.kind::f16 [%0], [%1], %2, %3, {%4, %4, %4, %4}, p;\n\t}"
        :: "r"(d), "r"(a_tmem), "l"(bd), "r"(idesc), "r"(0u), "r"(en) : "memory");
}
__device__ __forceinline__ uint64_t make_desc(uint32_t addr) {
    uint64_t d = (uint64_t(2) << 61) | (uint64_t(1) << 46) |
                 (uint64_t(64) << 32) | (uint64_t(1) << 16);
    return d | ((uint64_t)(addr >> 4) & 0x3FFF);
}
// idesc: F32 accum(bit4), BF16 a(bit7), BF16 b(bit10), N=64 (8<<17), M=128 (8<<24)
#define IDESC_ 0x08100490u
#endif  // HAS_TCGEN05

// ============================================================
// Kernel 1: global average pool
// ============================================================
__global__ void pool_kernel(const float* __restrict__ x) {
    int plane = blockIdx.x;
    const float4* p = (const float4*)(x + ((size_t)plane << 14));
    float s = 0.f;
    for (int i = threadIdx.x; i < (H_ * W_ / 4); i += 256) {
        float4 v = p[i];
        s += (v.x + v.y) + (v.z + v.w);
    }
#pragma unroll
    for (int o = 16; o; o >>= 1) s += __shfl_xor_sync(0xffffffffu, s, o);
    __shared__ float red[8];
    if ((threadIdx.x & 31) == 0) red[threadIdx.x >> 5] = s;
    __syncthreads();
    if (threadIdx.x == 0) {
        float t = 0.f;
#pragma unroll
        for (int i = 0; i < 8; i++) t += red[i];
        g_pooled[plane] = t * (1.f / (H_ * W_));
    }
}

// ============================================================
// Kernel 2: h = relu(pooled @ w1 + b1), one block per sample
// ============================================================
__global__ void mlp1_kernel(const float* __restrict__ w1, const float* __restrict__ b1) {
    int b = blockIdx.x;
    int a = threadIdx.x;     // 64 threads
    __shared__ float sp[CIN_];
    sp[a] = g_pooled[b * CIN_ + a];
    __syncthreads();
    float acc = b1[a];
#pragma unroll 16
    for (int k = 0; k < CIN_; k++) acc += sp[k] * w1[k * ADIM_ + a];
    g_hid[b * ADIM_ + a] = fmaxf(acc, 0.f);
}

// ============================================================
// Kernel 3: adapted weights -> fp32 (fallback) + bf16 hi/lo swizzled tiles
// ============================================================
__global__ void adapt_kernel(const float* __restrict__ base_w,
                             const float* __restrict__ w2,
                             const float* __restrict__ b2,
                             const float* __restrict__ scale_p) {
    __shared__ float sh[B_][ADIM_ + 1];
    __shared__ float sw2[ADIM_][8];
    int col0 = blockIdx.x * 8;
    for (int i = threadIdx.x; i < B_ * ADIM_; i += 256)
        sh[i >> 6][i & 63] = g_hid[i];
    for (int i = threadIdx.x; i < ADIM_ * 8; i += 256)
        sw2[i >> 3][i & 7] = w2[(size_t)(i >> 3) * KVOL_ + col0 + (i & 7)];
    __syncthreads();
    int j = threadIdx.x >> 5;
    int b = threadIdx.x & 31;
    int col = col0 + j;
    float acc = b2[col];
#pragma unroll
    for (int a = 0; a < ADIM_; a++) acc += sh[b][a] * sw2[a][j];
    float w = base_w[col] + scale_p[0] * tanhf(acc);
    g_wadapt[(size_t)b * KVOL_ + col] = w;
    // col = ((n*64+ci)*3+dy)*3+dx
    int t1 = col / 3, dx = col - 3 * t1;
    int t2 = t1 / 3, dy = t1 - 3 * t2;
    int ci = t2 & 63, n = t2 >> 6;
    __nv_bfloat16 hi = __float2bfloat16(w);
    __nv_bfloat16 lo = __float2bfloat16(w - __bfloat162float(hi));
    uint32_t off = swzB(n, dx * 64 + ci);
    size_t base = (size_t)((b * 3 + dy) * 2) * 24576;
    *(__nv_bfloat16*)(g_wB + base + off) = hi;
    *(__nv_bfloat16*)(g_wB + base + 24576 + off) = lo;
}

// ============================================================
// Kernel 4: tensor-core implicit conv (sm_103a), 544 threads
//   R12 structure (warp-specialized TS, 4-row sub-band, A shared
//   across dy) + TWO sub-bands per CTA: B staged ONCE, TMEM alloc
//   once, pipeline stays warm. Grid halves to (16, 32).
// ============================================================
#define MB_MDONE    8u
#define MB_AREADY   16u
#define SM_SCRATCH  1024u                 // uint32 [130][65] = 33800B
#define SCRATCH_END (1024u + 33800u)
#define T_B   0u                          // 3 dy x (hi 24576 + lo 24576)
#define T_SZ  147456u
#define SM_TOTAL (SCRATCH_END + 1024u + T_SZ)   // ~183.3KB -> 1 CTA/SM

#define TM_D   0u       // D: 4 tiles x 64 cols = 256
#define TM_AH  256u     // Ah: 96 cols
#define TM_AL  352u     // Al: 96 cols

#define NTHREADS 544    // 16 builder warps + 1 MMA warp
#define NROWS    6      // input rows per sub-band
#define NBANDS   2      // sub-bands per CTA (4 output rows each)

__global__ void __launch_bounds__(NTHREADS, 1)
conv_tc_kernel(const float* __restrict__ x,
               const float* __restrict__ base_b,
               float* __restrict__ y) {
#if HAS_TCGEN05
    extern __shared__ unsigned char sm[];
    __shared__ float sbb[COUT_];
    const uint32_t sbase = smem_u32(sm);
    uint32_t* scratch = (uint32_t*)(sm + SM_SCRATCH);

    const uint32_t tbase = (sbase + SCRATCH_END + 1023u) & ~1023u;
    unsigned char* tptr = sm + (tbase - sbase);

    const int tid = threadIdx.x;
    const int wid = tid >> 5;
    const int lid = tid & 31;
    const int h0 = blockIdx.x * 8;       // 8 output rows per CTA
    const int b  = blockIdx.y;
    const float* xb = x + ((size_t)b << 20);

    if (tid == 0) {
        MBAR_INIT(sbase + MB_MDONE, 1);
        MBAR_INIT(sbase + MB_AREADY, 1);
    }
    if (wid == 0) TC_ALLOC(sbase, 512);
    if (tid < COUT_) sbb[tid] = base_b[tid];
    if (tid < 64) { scratch[tid] = 0u; scratch[129 * 65 + tid] = 0u; }  // halo rows 0,129
    __syncthreads();
    uint32_t tmem;
    asm volatile("ld.shared.b32 %0, [%1];" : "=r"(tmem) : "r"(sbase));

    const uint64_t dB = make_desc(tbase + T_B);

    if (wid == 16) {
        // ================= MMA issue warp: 12 global rows =================
        for (int kg = 0; kg < NBANDS * NROWS; kg++) {
            const int ri = kg % NROWS;
            MBAR_WAIT(sbase + MB_AREADY, kg & 1);
            FENCE_ASYNC();
            TC_FENCE_AFTER();
            if (elect_one()) {
                int dylo = ri - 3 > 0 ? ri - 3 : 0;
                int dyhi = ri < 2 ? ri : 2;
                for (int dy = dylo; dy <= dyhi; dy++) {
                    int hh = ri - dy;                 // 0..3
                    uint32_t d = tmem + TM_D + hh * 64;
                    uint64_t bH = dB + (uint64_t)(dy * 3072);
                    uint64_t bL = bH + 1536;
#pragma unroll
                    for (int s = 0; s < 12; s++) {
                        uint64_t bo = (uint64_t)((s >> 2) * 512 + (s & 3) * 2);
                        mma_f16_ts(d, tmem + TM_AH + s * 8, bH + bo, IDESC_,
                                   !(dy == 0 && s == 0));
                    }
#pragma unroll
                    for (int s = 0; s < 12; s++) {
                        uint64_t bo = (uint64_t)((s >> 2) * 512 + (s & 3) * 2);
                        mma_f16_ts(d, tmem + TM_AL + s * 8, bH + bo, IDESC_, 1u);
                    }
#pragma unroll
                    for (int s = 0; s < 12; s++) {
                        uint64_t bo = (uint64_t)((s >> 2) * 512 + (s & 3) * 2);
                        mma_f16_ts(d, tmem + TM_AH + s * 8, bL + bo, IDESC_, 1u);
                    }
                }
                TC_COMMIT(sbase + MB_MDONE);
            }
        }
    } else {
        // ================= 16 builder warps =================
        // B prologue ONCE per CTA (3 dy x hi/lo, contiguous in g_wB)
        {
            const uint4* src = (const uint4*)(g_wB + (size_t)(b * 3) * 2 * 24576);
            uint4* dst = (uint4*)(tptr + T_B);
            for (int i = tid; i < (int)(T_SZ / 16); i += 512) dst[i] = src[i];
        }

        const int pf_w4 = tid & 31;
        const int ci_base = tid >> 5;        // ci = it*16 + ci_base (0..15)
        const int am = tid & 127;
        const int awg = tid >> 7;            // 0..3
        const uint32_t warp_off = (uint32_t)((tid & 127) >> 5) << 21;

        for (int band = 0; band < NBANDS; band++) {
            const int h0b = h0 + band * 4;

            float4 v[4];
            // load input row for ri=0 of this band (row = h0b-1; clamp)
            {
                int r = h0b - 1;
                bool valid = r >= 0;
                int rc = valid ? r : 0;
                const float4* xr4 = (const float4*)(xb + ((size_t)rc << 7));
#pragma unroll
                for (int it = 0; it < 4; it++) {
                    float4 t = xr4[((size_t)(it * 16 + ci_base) << 12) + pf_w4];
                    v[it] = valid ? t : make_float4(0.f, 0.f, 0.f, 0.f);
                }
            }

            for (int ri = 0; ri < NROWS; ri++) {
                const int kg = band * NROWS + ri;
                // stage scratch from registers
#pragma unroll
                for (int it = 0; it < 4; it++) {
                    float vv[4] = {v[it].x, v[it].y, v[it].z, v[it].w};
                    int ci = it * 16 + ci_base;
                    int wbase = (pf_w4 << 2) + 1;
#pragma unroll
                    for (int q = 0; q < 4; q++) {
                        __nv_bfloat16 hi = __float2bfloat16(vv[q]);
                        __nv_bfloat16 lo = __float2bfloat16(vv[q] - __bfloat162float(hi));
                        scratch[(wbase + q) * 65 + ci] =
                            (uint32_t)__bfloat16_as_ushort(hi) |
                            ((uint32_t)__bfloat16_as_ushort(lo) << 16);
                    }
                }
                BAR1_512();                  // scratch + (kg==0: B copy) visible

                // hoisted LDG: next input row within band
                if (ri + 1 < NROWS) {
                    int r = h0b + ri;
                    bool valid = r < H_;
                    int rc = valid ? r : (H_ - 1);
                    const float4* xr4 = (const float4*)(xb + ((size_t)rc << 7));
#pragma unroll
                    for (int it = 0; it < 4; it++) {
                        float4 t = xr4[((size_t)(it * 16 + ci_base) << 12) + pf_w4];
                        v[it] = valid ? t : make_float4(0.f, 0.f, 0.f, 0.f);
                    }
                }

                // wait prev global row's MMAs before overwriting A.
                // (band>0, ri==0: the inter-band epilogue already waited.)
                if (ri > 0) MBAR_WAIT(sbase + MB_MDONE, (kg - 1) & 1);

                // A build into TMEM (depends only on input row)
#pragma unroll
                for (int chunk = 0; chunk < 3; chunk++) {
                    int c0 = awg * 24 + chunk * 8;
                    uint32_t hi[8], lo[8];
#pragma unroll
                    for (int j = 0; j < 8; j++) {
                        int c = c0 + j;
                        int kk2 = 2 * c;
                        int dx = kk2 >> 6;
                        int ci = kk2 & 63;
                        const uint32_t* s2 = &scratch[(am + dx) * 65 + ci];
                        uint32_t w0 = s2[0], w1 = s2[1];
                        hi[j] = __byte_perm(w0, w1, 0x5410);
                        lo[j] = __byte_perm(w0, w1, 0x7632);
                    }
                    TC_ST_X8(tmem + TM_AH + c0 + warp_off, hi);
                    TC_ST_X8(tmem + TM_AL + c0 + warp_off, lo);
                }
                TC_WAIT_ST();
                TC_FENCE_BEFORE();
                BAR1_512();                  // all of A in TMEM
                if (tid == 0) MBAR_ARRIVE(sbase + MB_AREADY);
            }

            // band drain: last commit of this band has parity 1
            // (phases band*6 .. band*6+5; previous confirmed = band*6+4)
            MBAR_WAIT(sbase + MB_MDONE, 1);
            TC_FENCE_AFTER();

            // epilogue: warp w: subpartition = w&3 (HW), hh = w>>2 (0..3)
            {
                int sub = wid & 3, hh = wid >> 2;
                int m = sub * 32 + lid;
                int h = h0b + hh;
                float* yr = y + ((size_t)b << 20) + ((size_t)h << 7) + m;
                uint32_t r0[32], r1[32];
                TC_LD_X32(r0, tmem + TM_D + hh * 64);
                TC_LD_X32(r1, tmem + TM_D + hh * 64 + 32);
                TC_WAIT_LD();
#pragma unroll
                for (int c = 0; c < 32; c++)
                    yr[(size_t)c << 14] = __uint_as_float(r0[c]) + sbb[c];
#pragma unroll
                for (int c = 0; c < 32; c++)
                    yr[(size_t)(c + 32) << 14] = __uint_as_float(r1[c]) + sbb[c + 32];
            }
            TC_FENCE_BEFORE();
            BAR1_512();                      // D fully read before next band reuses it
        }
    }

    __syncthreads();
    if (wid == 0) TC_DEALLOC(tmem, 512);

#else  // -------- generic-PTX fallback: correct scalar conv --------
    const int tid = threadIdx.x;
    const int h0 = blockIdx.x * 8;
    const int b  = blockIdx.y;
    const float* xb = x + ((size_t)b << 20);
    const float* wgt_b = g_wadapt + (size_t)b * KVOL_;
    for (int idx = tid; idx < 8 * 128 * 64; idx += NTHREADS) {
        int w = idx & 127;
        int rest = idx >> 7;
        int co = rest & 63;
        int hh = rest >> 6;
        int h = h0 + hh;
        float acc = base_b[co];
        const float* wgt = wgt_b + co * 576;
        for (int ci = 0; ci < CIN_; ci++) {
            const float* xp = xb + ((size_t)ci << 14);
            const float* wp = wgt + ci * 9;
            for (int ky = 0; ky < 3; ky++) {
                int ih = h + ky - 1;
                if ((unsigned)ih >= (unsigned)H_) continue;
                for (int kx = 0; kx < 3; kx++) {
                    int iw = w + kx - 1;
                    if ((unsigned)iw >= (unsigned)W_) continue;
                    acc += xp[(ih << 7) + iw] * wp[ky * 3 + kx];
                }
            }
        }
        y[((size_t)b << 20) + ((size_t)co << 14) + ((size_t)h << 7) + w] = acc;
    }
#endif
}

// ============================================================
extern "C" void kernel_launch(void* const* d_in, const int* in_sizes, int n_in,
                              void* d_out, int out_size) {
    const float* x      = (const float*)d_in[0];
    const float* base_w = (const float*)d_in[1];
    const float* base_b = (const float*)d_in[2];
    const float* w1     = (const float*)d_in[3];
    const float* b1     = (const float*)d_in[4];
    const float* w2     = (const float*)d_in[5];
    const float* b2     = (const float*)d_in[6];
    const float* scale  = (const float*)d_in[7];
    float* y = (float*)d_out;

    cudaFuncSetAttribute(conv_tc_kernel,
                         cudaFuncAttributeMaxDynamicSharedMemorySize, SM_TOTAL);

    pool_kernel<<<B_ * CIN_, 256>>>(x);
    mlp1_kernel<<<B_, 64>>>(w1, b1);
    adapt_kernel<<<KVOL_ / 8, 256>>>(base_w, w2, b2, scale);
    conv_tc_kernel<<<dim3(H_ / 8, B_), NTHREADS, SM_TOTAL>>>(x, base_b, y);
}

// round 16
// speedup vs baseline: 1.3208x; 1.0803x over previous
#include <cuda_runtime.h>
#include <cuda_bf16.h>
#include <cstdint>

#define B_    32
#define CIN_  64
#define COUT_ 64
#define ADIM_ 64
#define H_    128
#define W_    128
#define KVOL_ (COUT_*CIN_*9)

// tcgen05 only exists under arch-specific (sm_103a/sm_100a) compilation.
#if defined(__CUDA_ARCH_FEAT_SM103_ALL) || defined(__CUDA_ARCH_FEAT_SM100_ALL) || \
    (defined(__CUDA_ARCH_SPECIFIC__))
#define HAS_TCGEN05 1
#else
#define HAS_TCGEN05 0
#endif

// ---------------- device scratch ----------------
__device__ float g_pooled[B_ * CIN_];
__device__ float g_hid[B_ * ADIM_];
__device__ float g_wadapt[B_ * KVOL_];   // fp32 weights (fallback path)
// pre-swizzled bf16 weight tiles: [b][dy][hi/lo] x 24576 bytes (64 x 192, blocked-atom SW128)
__device__ unsigned char g_wB[B_ * 3 * 2 * 24576];

// ---------------- helpers ----------------
__device__ __forceinline__ uint32_t smem_u32(const void* p) {
    uint32_t a;
    asm("{ .reg .u64 t; cvta.to.shared.u64 t, %1; cvt.u32.u64 %0, t; }" : "=r"(a) : "l"(p));
    return a;
}
__device__ __forceinline__ uint32_t swzB(int n, int k) {   // 64 rows x 192 k
    uint32_t byte = (uint32_t)(k >> 6) * 8192u + ((uint32_t)(n >> 3) << 10) +
                    ((uint32_t)(n & 7) << 7) + ((uint32_t)(k & 63) << 1);
    return byte ^ ((byte >> 3) & 0x70u);
}

#if HAS_TCGEN05
__device__ __forceinline__ uint32_t elect_one() {
    uint32_t pred;
    asm volatile("{\n\t.reg .pred p;\n\telect.sync _|p, 0xFFFFFFFF;\n\t"
                 "selp.b32 %0, 1, 0, p;\n\t}" : "=r"(pred));
    return pred;
}
#define MBAR_INIT(a, c) asm volatile("mbarrier.init.shared.b64 [%0], %1;" :: "r"(a), "r"(c) : "memory")
#define MBAR_ARRIVE(a)  asm volatile("mbarrier.arrive.shared.b64 _, [%0];" :: "r"(a) : "memory")
#define MBAR_WAIT(a, ph) do {                                                                   \
    uint32_t _m = (a), _p = (ph), _d;                                                           \
    asm volatile("{\n\t.reg .pred p;\n\t"                                                       \
        "mbarrier.try_wait.parity.acquire.cta.shared::cta.b64 p, [%1], %2;\n\t"                 \
        "selp.b32 %0, 1, 0, p;\n\t}" : "=r"(_d) : "r"(_m), "r"(_p) : "memory");                 \
    if (!_d) {                                                                                  \
        asm volatile("{\n\t.reg .pred P1;\n\t"                                                  \
            "WL_%=:\n\t"                                                                        \
            "mbarrier.try_wait.parity.acquire.cta.shared::cta.b64 P1, [%0], %1, 0x989680;\n\t"  \
            "@P1 bra.uni WD_%=;\n\t"                                                            \
            "bra.uni WL_%=;\n\t"                                                                \
            "WD_%=:\n\t}" :: "r"(_m), "r"(_p) : "memory");                                      \
    }                                                                                           \
} while (0)
#define BAR1_512() asm volatile("bar.sync 1, 512;" ::: "memory")
#define TC_ALLOC(sa, n)   asm volatile("tcgen05.alloc.cta_group::1.sync.aligned.shared::cta.b32 [%0], %1;" :: "r"(sa), "r"(n) : "memory")
#define TC_DEALLOC(t, n)  asm volatile("tcgen05.dealloc.cta_group::1.sync.aligned.b32 %0, %1;" :: "r"(t), "r"(n))
#define TC_COMMIT(mb)     asm volatile("tcgen05.commit.cta_group::1.mbarrier::arrive::one.shared::cluster.b64 [%0];" :: "r"(mb) : "memory")
#define TC_FENCE_AFTER()  asm volatile("tcgen05.fence::after_thread_sync;" ::: "memory")
#define TC_FENCE_BEFORE() asm volatile("tcgen05.fence::before_thread_sync;" ::: "memory")
#define TC_WAIT_LD()      asm volatile("tcgen05.wait::ld.sync.aligned;" ::: "memory")
#define TC_WAIT_ST()      asm volatile("tcgen05.wait::st.sync.aligned;" ::: "memory")
#define FENCE_ASYNC()     asm volatile("fence.proxy.async.shared::cta;" ::: "memory")

#define TC_LD_X32(r, ta) \
    asm volatile("tcgen05.ld.sync.aligned.32x32b.x32.b32 " \
        "{%0, %1, %2, %3, %4, %5, %6, %7, %8, %9, %10, %11, %12, %13, %14, %15, " \
        "%16, %17, %18, %19, %20, %21, %22, %23, %24, %25, %26, %27, %28, %29, %30, %31}, [%32];" \
        : "=r"((r)[0]),  "=r"((r)[1]),  "=r"((r)[2]),  "=r"((r)[3]), \
          "=r"((r)[4]),  "=r"((r)[5]),  "=r"((r)[6]),  "=r"((r)[7]), \
          "=r"((r)[8]),  "=r"((r)[9]),  "=r"((r)[10]), "=r"((r)[11]), \
          "=r"((r)[12]), "=r"((r)[13]), "=r"((r)[14]), "=r"((r)[15]), \
          "=r"((r)[16]), "=r"((r)[17]), "=r"((r)[18]), "=r"((r)[19]), \
          "=r"((r)[20]), "=r"((r)[21]), "=r"((r)[22]), "=r"((r)[23]), \
          "=r"((r)[24]), "=r"((r)[25]), "=r"((r)[26]), "=r"((r)[27]), \
          "=r"((r)[28]), "=r"((r)[29]), "=r"((r)[30]), "=r"((r)[31]) \
        : "r"(ta))

#define TC_ST_X8(ta, r) \
    asm volatile("tcgen05.st.sync.aligned.32x32b.x8.b32 [%0], " \
        "{%1, %2, %3, %4, %5, %6, %7, %8};" \
        :: "r"(ta), \
           "r"((r)[0]), "r"((r)[1]), "r"((r)[2]), "r"((r)[3]), \
           "r"((r)[4]), "r"((r)[5]), "r"((r)[6]), "r"((r)[7]) \
        : "memory")

// TS-mode f16 MMA: A in TMEM, B in smem (pattern: test_mma.cu / test_mma_iter.cu)
__device__ __forceinline__ void mma_f16_ts(uint32_t d, uint32_t a_tmem, uint64_t bd,
                                           uint32_t idesc, uint32_t en) {
    asm volatile("{\n\t.reg .pred p;\n\tsetp.ne.u32 p, %5, 0;\n\t"
        "tcgen05.mma.cta_group::1.kind::f16 [%0], [%1], %2, %3, {%4, %4, %4, %4}, p;\n\t}"
        :: "r"(d), "r"(a_tmem), "l"(bd), "r"(idesc), "r"(0u), "r"(en) : "memory");
}
__device__ __forceinline__ uint64_t make_desc(uint32_t addr) {
    uint64_t d = (uint64_t(2) << 61) | (uint64_t(1) << 46) |
                 (uint64_t(64) << 32) | (uint64_t(1) << 16);
    return d | ((uint64_t)(addr >> 4) & 0x3FFF);
}
// idesc: F32 accum(bit4), BF16 a(bit7), BF16 b(bit10), N=64 (8<<17), M=128 (8<<24)
#define IDESC_ 0x08100490u
#endif  // HAS_TCGEN05

// ============================================================
// Kernel 1: global average pool
// ============================================================
__global__ void pool_kernel(const float* __restrict__ x) {
    int plane = blockIdx.x;
    const float4* p = (const float4*)(x + ((size_t)plane << 14));
    float s = 0.f;
    for (int i = threadIdx.x; i < (H_ * W_ / 4); i += 256) {
        float4 v = p[i];
        s += (v.x + v.y) + (v.z + v.w);
    }
#pragma unroll
    for (int o = 16; o; o >>= 1) s += __shfl_xor_sync(0xffffffffu, s, o);
    __shared__ float red[8];
    if ((threadIdx.x & 31) == 0) red[threadIdx.x >> 5] = s;
    __syncthreads();
    if (threadIdx.x == 0) {
        float t = 0.f;
#pragma unroll
        for (int i = 0; i < 8; i++) t += red[i];
        g_pooled[plane] = t * (1.f / (H_ * W_));
    }
}

// ============================================================
// Kernel 2: h = relu(pooled @ w1 + b1), one block per sample
// ============================================================
__global__ void mlp1_kernel(const float* __restrict__ w1, const float* __restrict__ b1) {
    int b = blockIdx.x;
    int a = threadIdx.x;     // 64 threads
    __shared__ float sp[CIN_];
    sp[a] = g_pooled[b * CIN_ + a];
    __syncthreads();
    float acc = b1[a];
#pragma unroll 16
    for (int k = 0; k < CIN_; k++) acc += sp[k] * w1[k * ADIM_ + a];
    g_hid[b * ADIM_ + a] = fmaxf(acc, 0.f);
}

// ============================================================
// Kernel 3: adapted weights (32-col blocks: w2 reads full 128B sectors)
// ============================================================
__global__ void adapt_kernel(const float* __restrict__ base_w,
                             const float* __restrict__ w2,
                             const float* __restrict__ b2,
                             const float* __restrict__ scale_p) {
    __shared__ float sh[B_][ADIM_ + 1];
    __shared__ float sw2[ADIM_][33];
    int col0 = blockIdx.x * 32;
    for (int i = threadIdx.x; i < B_ * ADIM_; i += 256)
        sh[i >> 6][i & 63] = g_hid[i];
    for (int i = threadIdx.x; i < ADIM_ * 32; i += 256)
        sw2[i >> 5][i & 31] = w2[(size_t)(i >> 5) * KVOL_ + col0 + (i & 31)];
    __syncthreads();
    int j = threadIdx.x & 31;        // column
    int bq = threadIdx.x >> 5;       // 0..7
    int col = col0 + j;
    float bias = b2[col];
    float bw = base_w[col];
    float sc = scale_p[0];
    // col = ((n*64+ci)*3+dy)*3+dx
    int t1 = col / 3, dx = col - 3 * t1;
    int t2 = t1 / 3, dy = t1 - 3 * t2;
    int ci = t2 & 63, n = t2 >> 6;
    uint32_t off = swzB(n, dx * 64 + ci);
#pragma unroll
    for (int q = 0; q < 4; q++) {
        int b = bq * 4 + q;
        float acc = bias;
#pragma unroll 16
        for (int a = 0; a < ADIM_; a++) acc += sh[b][a] * sw2[a][j];
        float w = bw + sc * tanhf(acc);
        g_wadapt[(size_t)b * KVOL_ + col] = w;
        __nv_bfloat16 hi = __float2bfloat16(w);
        __nv_bfloat16 lo = __float2bfloat16(w - __bfloat162float(hi));
        size_t base = (size_t)((b * 3 + dy) * 2) * 24576;
        *(__nv_bfloat16*)(g_wB + base + off) = hi;
        *(__nv_bfloat16*)(g_wB + base + 24576 + off) = lo;
    }
}

// ============================================================
// Kernel 4: tensor-core implicit conv (sm_103a), 544 threads
//   Warp-specialized TS + DOUBLE-BUFFERED A + 4 bands of 2 rows.
//   B staged once per CTA. TMEM: D 128 + A0 192 + A1 192 = 512.
//   kg = band*4 + ri (16 input rows); commit(kg) -> MDONE[kg&1]
//   index kg>>1. Builder(kg>=2) waits index (kg-2)>>1 on MDONE[kg&1].
//   Epilogue(band) waits index 2b+1 (parity 1) on both MDONEs.
// ============================================================
#define MB_MDONE0   8u
#define MB_MDONE1   16u
#define MB_AREADY   24u
#define SM_SCRATCH  1024u                 // uint32 [130][65] = 33800B
#define SCRATCH_END (1024u + 33800u)
#define T_B   0u                          // 3 dy x (hi 24576 + lo 24576)
#define T_SZ  147456u
#define SM_TOTAL (SCRATCH_END + 1024u + T_SZ)   // ~183.3KB -> 1 CTA/SM

#define TM_D   0u        // D: 2 tiles x 64 cols = 128
#define TM_A0  128u      // buf0: Ah @128, Al @224
#define TM_A1  320u      // buf1: Ah @320, Al @416

#define NTHREADS 544     // 16 builder warps + 1 MMA warp
#define NBANDS   4       // bands of 2 output rows
#define BROWS    4       // input rows per band

__global__ void __launch_bounds__(NTHREADS, 1)
conv_tc_kernel(const float* __restrict__ x,
               const float* __restrict__ base_b,
               float* __restrict__ y) {
#if HAS_TCGEN05
    extern __shared__ unsigned char sm[];
    __shared__ float sbb[COUT_];
    const uint32_t sbase = smem_u32(sm);
    uint32_t* scratch = (uint32_t*)(sm + SM_SCRATCH);

    const uint32_t tbase = (sbase + SCRATCH_END + 1023u) & ~1023u;
    unsigned char* tptr = sm + (tbase - sbase);

    const int tid = threadIdx.x;
    const int wid = tid >> 5;
    const int lid = tid & 31;
    const int h0 = blockIdx.x * 8;       // 8 output rows per CTA
    const int b  = blockIdx.y;
    const float* xb = x + ((size_t)b << 20);

    if (tid == 0) {
        MBAR_INIT(sbase + MB_MDONE0, 1);
        MBAR_INIT(sbase + MB_MDONE1, 1);
        MBAR_INIT(sbase + MB_AREADY, 1);
    }
    if (wid == 0) TC_ALLOC(sbase, 512);
    if (tid < COUT_) sbb[tid] = base_b[tid];
    if (tid < 64) { scratch[tid] = 0u; scratch[129 * 65 + tid] = 0u; }  // halo rows 0,129
    __syncthreads();
    uint32_t tmem;
    asm volatile("ld.shared.b32 %0, [%1];" : "=r"(tmem) : "r"(sbase));

    const uint64_t dB = make_desc(tbase + T_B);

    if (wid == 16) {
        // ================= MMA issue warp: 16 global rows =================
        for (int kg = 0; kg < NBANDS * BROWS; kg++) {
            const int ri = kg & 3;
            MBAR_WAIT(sbase + MB_AREADY, kg & 1);
            FENCE_ASYNC();
            TC_FENCE_AFTER();
            if (elect_one()) {
                uint32_t aBase = tmem + ((kg & 1) ? TM_A1 : TM_A0);
                int dylo = ri - 1 > 0 ? ri - 1 : 0;
                int dyhi = ri < 2 ? ri : 2;
                for (int dy = dylo; dy <= dyhi; dy++) {
                    int hh = ri - dy;                 // 0 or 1
                    uint32_t d = tmem + TM_D + hh * 64;
                    uint64_t bH = dB + (uint64_t)(dy * 3072);
                    uint64_t bL = bH + 1536;
#pragma unroll
                    for (int s = 0; s < 12; s++) {
                        uint64_t bo = (uint64_t)((s >> 2) * 512 + (s & 3) * 2);
                        mma_f16_ts(d, aBase + s * 8, bH + bo, IDESC_,
                                   !(dy == 0 && s == 0));
                    }
#pragma unroll
                    for (int s = 0; s < 12; s++) {
                        uint64_t bo = (uint64_t)((s >> 2) * 512 + (s & 3) * 2);
                        mma_f16_ts(d, aBase + 96 + s * 8, bH + bo, IDESC_, 1u);
                    }
#pragma unroll
                    for (int s = 0; s < 12; s++) {
                        uint64_t bo = (uint64_t)((s >> 2) * 512 + (s & 3) * 2);
                        mma_f16_ts(d, aBase + s * 8, bL + bo, IDESC_, 1u);
                    }
                }
                TC_COMMIT(sbase + ((kg & 1) ? MB_MDONE1 : MB_MDONE0));
            }
        }
    } else {
        // ================= 16 builder warps =================
        // B prologue ONCE per CTA
        {
            const uint4* src = (const uint4*)(g_wB + (size_t)(b * 3) * 2 * 24576);
            uint4* dst = (uint4*)(tptr + T_B);
            for (int i = tid; i < (int)(T_SZ / 16); i += 512) dst[i] = src[i];
        }

        const int pf_w4 = tid & 31;
        const int ci_base = tid >> 5;        // ci = it*16 + ci_base (0..15)
        const int am = tid & 127;
        const int awg = tid >> 7;            // 0..3
        const uint32_t warp_off = (uint32_t)((tid & 127) >> 5) << 21;

        for (int band = 0; band < NBANDS; band++) {
            const int h0b = h0 + band * 2;

            float4 v[4];
            // load input row for ri=0 (row = h0b-1; clamp, zero-fill)
            {
                int r = h0b - 1;
                bool valid = r >= 0;
                int rc = valid ? r : 0;
                const float4* xr4 = (const float4*)(xb + ((size_t)rc << 7));
#pragma unroll
                for (int it = 0; it < 4; it++) {
                    float4 t = xr4[((size_t)(it * 16 + ci_base) << 12) + pf_w4];
                    v[it] = valid ? t : make_float4(0.f, 0.f, 0.f, 0.f);
                }
            }

            for (int ri = 0; ri < BROWS; ri++) {
                const int kg = band * BROWS + ri;
                // stage scratch from registers
#pragma unroll
                for (int it = 0; it < 4; it++) {
                    float vv[4] = {v[it].x, v[it].y, v[it].z, v[it].w};
                    int ci = it * 16 + ci_base;
                    int wbase = (pf_w4 << 2) + 1;
#pragma unroll
                    for (int q = 0; q < 4; q++) {
                        __nv_bfloat16 hi = __float2bfloat16(vv[q]);
                        __nv_bfloat16 lo = __float2bfloat16(vv[q] - __bfloat162float(hi));
                        scratch[(wbase + q) * 65 + ci] =
                            (uint32_t)__bfloat16_as_ushort(hi) |
                            ((uint32_t)__bfloat16_as_ushort(lo) << 16);
                    }
                }
                BAR1_512();                  // scratch + (kg==0: B copy) visible

                // hoisted LDG: next input row within band
                if (ri + 1 < BROWS) {
                    int r = h0b + ri;
                    bool valid = r < H_;
                    int rc = valid ? r : (H_ - 1);
                    const float4* xr4 = (const float4*)(xb + ((size_t)rc << 7));
#pragma unroll
                    for (int it = 0; it < 4; it++) {
                        float4 t = xr4[((size_t)(it * 16 + ci_base) << 12) + pf_w4];
                        v[it] = valid ? t : make_float4(0.f, 0.f, 0.f, 0.f);
                    }
                }

                // wait: commit(kg-2) on MDONE[kg&1], index (kg-2)>>1
                if (kg >= 2)
                    MBAR_WAIT(sbase + ((kg & 1) ? MB_MDONE1 : MB_MDONE0),
                              ((kg - 2) >> 1) & 1);

                // A build into TMEM buffer kg&1
                {
                    uint32_t aBase = tmem + ((kg & 1) ? TM_A1 : TM_A0) + warp_off;
#pragma unroll
                    for (int chunk = 0; chunk < 3; chunk++) {
                        int c0 = awg * 24 + chunk * 8;
                        uint32_t hi[8], lo[8];
#pragma unroll
                        for (int j = 0; j < 8; j++) {
                            int c = c0 + j;
                            int kk2 = 2 * c;
                            int dx = kk2 >> 6;
                            int ci = kk2 & 63;
                            const uint32_t* s2 = &scratch[(am + dx) * 65 + ci];
                            uint32_t w0 = s2[0], w1 = s2[1];
                            hi[j] = __byte_perm(w0, w1, 0x5410);
                            lo[j] = __byte_perm(w0, w1, 0x7632);
                        }
                        TC_ST_X8(aBase + c0, hi);
                        TC_ST_X8(aBase + 96 + c0, lo);
                    }
                }
                TC_WAIT_ST();
                TC_FENCE_BEFORE();
                BAR1_512();                  // all of A(kg) in TMEM
                if (tid == 0) MBAR_ARRIVE(sbase + MB_AREADY);
            }

            // band drain: commits (4b+2 -> MDONE0 idx 2b+1) and
            // (4b+3 -> MDONE1 idx 2b+1); both parity 1.
            MBAR_WAIT(sbase + MB_MDONE0, 1);
            MBAR_WAIT(sbase + MB_MDONE1, 1);
            TC_FENCE_AFTER();

            // epilogue: warp w: subpartition = w&3 (HW-implied),
            //           hh = (w>>2)&1, half = w>>3
            {
                int sub = wid & 3, hh = (wid >> 2) & 1, half = wid >> 3;
                int m = sub * 32 + lid;
                int h = h0b + hh;
                float* yr = y + ((size_t)b << 20) + ((size_t)h << 7) + m;
                uint32_t r0[32];
                TC_LD_X32(r0, tmem + TM_D + hh * 64 + half * 32);
                TC_WAIT_LD();
#pragma unroll
                for (int c = 0; c < 32; c++) {
                    int co = half * 32 + c;
                    yr[(size_t)co << 14] = __uint_as_float(r0[c]) + sbb[co];
                }
            }
            TC_FENCE_BEFORE();
            BAR1_512();                      // D fully read before next band
        }
    }

    __syncthreads();
    if (wid == 0) TC_DEALLOC(tmem, 512);

#else  // -------- generic-PTX fallback: correct scalar conv --------
    const int tid = threadIdx.x;
    const int h0 = blockIdx.x * 8;
    const int b  = blockIdx.y;
    const float* xb = x + ((size_t)b << 20);
    const float* wgt_b = g_wadapt + (size_t)b * KVOL_;
    for (int idx = tid; idx < 8 * 128 * 64; idx += NTHREADS) {
        int w = idx & 127;
        int rest = idx >> 7;
        int co = rest & 63;
        int hh = rest >> 6;
        int h = h0 + hh;
        float acc = base_b[co];
        const float* wgt = wgt_b + co * 576;
        for (int ci = 0; ci < CIN_; ci++) {
            const float* xp = xb + ((size_t)ci << 14);
            const float* wp = wgt + ci * 9;
            for (int ky = 0; ky < 3; ky++) {
                int ih = h + ky - 1;
                if ((unsigned)ih >= (unsigned)H_) continue;
                for (int kx = 0; kx < 3; kx++) {
                    int iw = w + kx - 1;
                    if ((unsigned)iw >= (unsigned)W_) continue;
                    acc += xp[(ih << 7) + iw] * wp[ky * 3 + kx];
                }
            }
        }
        y[((size_t)b << 20) + ((size_t)co << 14) + ((size_t)h << 7) + w] = acc;
    }
#endif
}

// ============================================================
extern "C" void kernel_launch(void* const* d_in, const int* in_sizes, int n_in,
                              void* d_out, int out_size) {
    const float* x      = (const float*)d_in[0];
    const float* base_w = (const float*)d_in[1];
    const float* base_b = (const float*)d_in[2];
    const float* w1     = (const float*)d_in[3];
    const float* b1     = (const float*)d_in[4];
    const float* w2     = (const float*)d_in[5];
    const float* b2     = (const float*)d_in[6];
    const float* scale  = (const float*)d_in[7];
    float* y = (float*)d_out;

    cudaFuncSetAttribute(conv_tc_kernel,
                         cudaFuncAttributeMaxDynamicSharedMemorySize, SM_TOTAL);

    pool_kernel<<<B_ * CIN_, 256>>>(x);
    mlp1_kernel<<<B_, 64>>>(w1, b1);
    adapt_kernel<<<KVOL_ / 32, 256>>>(base_w, w2, b2, scale);
    conv_tc_kernel<<<dim3(H_ / 8, B_), NTHREADS, SM_TOTAL>>>(x, base_b, y);
}

// round 17
// speedup vs baseline: 1.3661x; 1.0343x over previous
#include <cuda_runtime.h>
#include <cuda_bf16.h>
#include <cstdint>

#define B_    32
#define CIN_  64
#define COUT_ 64
#define ADIM_ 64
#define H_    128
#define W_    128
#define KVOL_ (COUT_*CIN_*9)

// tcgen05 only exists under arch-specific (sm_103a/sm_100a) compilation.
#if defined(__CUDA_ARCH_FEAT_SM103_ALL) || defined(__CUDA_ARCH_FEAT_SM100_ALL) || \
    (defined(__CUDA_ARCH_SPECIFIC__))
#define HAS_TCGEN05 1
#else
#define HAS_TCGEN05 0
#endif

// ---------------- device scratch ----------------
__device__ float g_pooled[B_ * CIN_];
__device__ float g_hid[B_ * ADIM_];
__device__ float g_wadapt[B_ * KVOL_];   // fp32 weights (fallback path)
// pre-swizzled bf16 weight tiles: [b][dy][hi/lo] x 24576 bytes (64 x 192, blocked-atom SW128)
__device__ unsigned char g_wB[B_ * 3 * 2 * 24576];

// ---------------- helpers ----------------
__device__ __forceinline__ uint32_t smem_u32(const void* p) {
    uint32_t a;
    asm("{ .reg .u64 t; cvta.to.shared.u64 t, %1; cvt.u32.u64 %0, t; }" : "=r"(a) : "l"(p));
    return a;
}
__device__ __forceinline__ uint32_t swzB(int n, int k) {   // 64 rows x 192 k
    uint32_t byte = (uint32_t)(k >> 6) * 8192u + ((uint32_t)(n >> 3) << 10) +
                    ((uint32_t)(n & 7) << 7) + ((uint32_t)(k & 63) << 1);
    return byte ^ ((byte >> 3) & 0x70u);
}

#if HAS_TCGEN05
__device__ __forceinline__ uint32_t elect_one() {
    uint32_t pred;
    asm volatile("{\n\t.reg .pred p;\n\telect.sync _|p, 0xFFFFFFFF;\n\t"
                 "selp.b32 %0, 1, 0, p;\n\t}" : "=r"(pred));
    return pred;
}
#define MBAR_INIT(a, c) asm volatile("mbarrier.init.shared.b64 [%0], %1;" :: "r"(a), "r"(c) : "memory")
#define MBAR_ARRIVE(a)  asm volatile("mbarrier.arrive.shared.b64 _, [%0];" :: "r"(a) : "memory")
#define MBAR_WAIT(a, ph) do {                                                                   \
    uint32_t _m = (a), _p = (ph), _d;                                                           \
    asm volatile("{\n\t.reg .pred p;\n\t"                                                       \
        "mbarrier.try_wait.parity.acquire.cta.shared::cta.b64 p, [%1], %2;\n\t"                 \
        "selp.b32 %0, 1, 0, p;\n\t}" : "=r"(_d) : "r"(_m), "r"(_p) : "memory");                 \
    if (!_d) {                                                                                  \
        asm volatile("{\n\t.reg .pred P1;\n\t"                                                  \
            "WL_%=:\n\t"                                                                        \
            "mbarrier.try_wait.parity.acquire.cta.shared::cta.b64 P1, [%0], %1, 0x989680;\n\t"  \
            "@P1 bra.uni WD_%=;\n\t"                                                            \
            "bra.uni WL_%=;\n\t"                                                                \
            "WD_%=:\n\t}" :: "r"(_m), "r"(_p) : "memory");                                      \
    }                                                                                           \
} while (0)
#define BAR1_512() asm volatile("bar.sync 1, 512;" ::: "memory")
#define TC_ALLOC(sa, n)   asm volatile("tcgen05.alloc.cta_group::1.sync.aligned.shared::cta.b32 [%0], %1;" :: "r"(sa), "r"(n) : "memory")
#define TC_DEALLOC(t, n)  asm volatile("tcgen05.dealloc.cta_group::1.sync.aligned.b32 %0, %1;" :: "r"(t), "r"(n))
#define TC_COMMIT(mb)     asm volatile("tcgen05.commit.cta_group::1.mbarrier::arrive::one.shared::cluster.b64 [%0];" :: "r"(mb) : "memory")
#define TC_FENCE_AFTER()  asm volatile("tcgen05.fence::after_thread_sync;" ::: "memory")
#define TC_FENCE_BEFORE() asm volatile("tcgen05.fence::before_thread_sync;" ::: "memory")
#define TC_WAIT_LD()      asm volatile("tcgen05.wait::ld.sync.aligned;" ::: "memory")
#define TC_WAIT_ST()      asm volatile("tcgen05.wait::st.sync.aligned;" ::: "memory")
#define FENCE_ASYNC()     asm volatile("fence.proxy.async.shared::cta;" ::: "memory")

#define TC_LD_X32(r, ta) \
    asm volatile("tcgen05.ld.sync.aligned.32x32b.x32.b32 " \
        "{%0, %1, %2, %3, %4, %5, %6, %7, %8, %9, %10, %11, %12, %13, %14, %15, " \
        "%16, %17, %18, %19, %20, %21, %22, %23, %24, %25, %26, %27, %28, %29, %30, %31}, [%32];" \
        : "=r"((r)[0]),  "=r"((r)[1]),  "=r"((r)[2]),  "=r"((r)[3]), \
          "=r"((r)[4]),  "=r"((r)[5]),  "=r"((r)[6]),  "=r"((r)[7]), \
          "=r"((r)[8]),  "=r"((r)[9]),  "=r"((r)[10]), "=r"((r)[11]), \
          "=r"((r)[12]), "=r"((r)[13]), "=r"((r)[14]), "=r"((r)[15]), \
          "=r"((r)[16]), "=r"((r)[17]), "=r"((r)[18]), "=r"((r)[19]), \
          "=r"((r)[20]), "=r"((r)[21]), "=r"((r)[22]), "=r"((r)[23]), \
          "=r"((r)[24]), "=r"((r)[25]), "=r"((r)[26]), "=r"((r)[27]), \
          "=r"((r)[28]), "=r"((r)[29]), "=r"((r)[30]), "=r"((r)[31]) \
        : "r"(ta))

#define TC_ST_X8(ta, r) \
    asm volatile("tcgen05.st.sync.aligned.32x32b.x8.b32 [%0], " \
        "{%1, %2, %3, %4, %5, %6, %7, %8};" \
        :: "r"(ta), \
           "r"((r)[0]), "r"((r)[1]), "r"((r)[2]), "r"((r)[3]), \
           "r"((r)[4]), "r"((r)[5]), "r"((r)[6]), "r"((r)[7]) \
        : "memory")

// TS-mode f16 MMA: A in TMEM, B in smem (pattern: test_mma.cu / test_mma_iter.cu)
__device__ __forceinline__ void mma_f16_ts(uint32_t d, uint32_t a_tmem, uint64_t bd,
                                           uint32_t idesc, uint32_t en) {
    asm volatile("{\n\t.reg .pred p;\n\tsetp.ne.u32 p, %5, 0;\n\t"
        "tcgen05.mma.cta_group::1.kind::f16 [%0], [%1], %2, %3, {%4, %4, %4, %4}, p;\n\t}"
        :: "r"(d), "r"(a_tmem), "l"(bd), "r"(idesc), "r"(0u), "r"(en) : "memory");
}
__device__ __forceinline__ uint64_t make_desc(uint32_t addr) {
    uint64_t d = (uint64_t(2) << 61) | (uint64_t(1) << 46) |
                 (uint64_t(64) << 32) | (uint64_t(1) << 16);
    return d | ((uint64_t)(addr >> 4) & 0x3FFF);
}
// idesc: F32 accum(bit4), BF16 a(bit7), BF16 b(bit10), N=64 (8<<17), M=128 (8<<24)
#define IDESC_ 0x08100490u
#endif  // HAS_TCGEN05

// ============================================================
// Kernel 1: global average pool
// ============================================================
__global__ void pool_kernel(const float* __restrict__ x) {
    int plane = blockIdx.x;
    const float4* p = (const float4*)(x + ((size_t)plane << 14));
    float s = 0.f;
    for (int i = threadIdx.x; i < (H_ * W_ / 4); i += 256) {
        float4 v = p[i];
        s += (v.x + v.y) + (v.z + v.w);
    }
#pragma unroll
    for (int o = 16; o; o >>= 1) s += __shfl_xor_sync(0xffffffffu, s, o);
    __shared__ float red[8];
    if ((threadIdx.x & 31) == 0) red[threadIdx.x >> 5] = s;
    __syncthreads();
    if (threadIdx.x == 0) {
        float t = 0.f;
#pragma unroll
        for (int i = 0; i < 8; i++) t += red[i];
        g_pooled[plane] = t * (1.f / (H_ * W_));
    }
}

// ============================================================
// Kernel 2: h = relu(pooled @ w1 + b1), one block per sample
// ============================================================
__global__ void mlp1_kernel(const float* __restrict__ w1, const float* __restrict__ b1) {
    int b = blockIdx.x;
    int a = threadIdx.x;     // 64 threads
    __shared__ float sp[CIN_];
    sp[a] = g_pooled[b * CIN_ + a];
    __syncthreads();
    float acc = b1[a];
#pragma unroll 16
    for (int k = 0; k < CIN_; k++) acc += sp[k] * w1[k * ADIM_ + a];
    g_hid[b * ADIM_ + a] = fmaxf(acc, 0.f);
}

// ============================================================
// Kernel 3: adapted weights (32-col blocks: w2 reads full 128B sectors)
// ============================================================
__global__ void adapt_kernel(const float* __restrict__ base_w,
                             const float* __restrict__ w2,
                             const float* __restrict__ b2,
                             const float* __restrict__ scale_p) {
    __shared__ float sh[B_][ADIM_ + 1];
    __shared__ float sw2[ADIM_][33];
    int col0 = blockIdx.x * 32;
    for (int i = threadIdx.x; i < B_ * ADIM_; i += 256)
        sh[i >> 6][i & 63] = g_hid[i];
    for (int i = threadIdx.x; i < ADIM_ * 32; i += 256)
        sw2[i >> 5][i & 31] = w2[(size_t)(i >> 5) * KVOL_ + col0 + (i & 31)];
    __syncthreads();
    int j = threadIdx.x & 31;        // column
    int bq = threadIdx.x >> 5;       // 0..7
    int col = col0 + j;
    float bias = b2[col];
    float bw = base_w[col];
    float sc = scale_p[0];
    // col = ((n*64+ci)*3+dy)*3+dx
    int t1 = col / 3, dx = col - 3 * t1;
    int t2 = t1 / 3, dy = t1 - 3 * t2;
    int ci = t2 & 63, n = t2 >> 6;
    uint32_t off = swzB(n, dx * 64 + ci);
#pragma unroll
    for (int q = 0; q < 4; q++) {
        int b = bq * 4 + q;
        float acc = bias;
#pragma unroll 16
        for (int a = 0; a < ADIM_; a++) acc += sh[b][a] * sw2[a][j];
        float w = bw + sc * tanhf(acc);
        g_wadapt[(size_t)b * KVOL_ + col] = w;
        __nv_bfloat16 hi = __float2bfloat16(w);
        __nv_bfloat16 lo = __float2bfloat16(w - __bfloat162float(hi));
        size_t base = (size_t)((b * 3 + dy) * 2) * 24576;
        *(__nv_bfloat16*)(g_wB + base + off) = hi;
        *(__nv_bfloat16*)(g_wB + base + 24576 + off) = lo;
    }
}

// ============================================================
// Kernel 4: tensor-core implicit conv (sm_103a), 544 threads
//   R15 structure (proven best conv): warp-specialized TS, A shared
//   across dy, single-buffered A, TWO 4-row sub-bands per CTA,
//   B staged once. TMEM: D 256 + Ah 96 + Al 96 = 448.
// ============================================================
#define MB_MDONE    8u
#define MB_AREADY   16u
#define SM_SCRATCH  1024u                 // uint32 [130][65] = 33800B
#define SCRATCH_END (1024u + 33800u)
#define T_B   0u                          // 3 dy x (hi 24576 + lo 24576)
#define T_SZ  147456u
#define SM_TOTAL (SCRATCH_END + 1024u + T_SZ)   // ~183.3KB -> 1 CTA/SM

#define TM_D   0u       // D: 4 tiles x 64 cols = 256
#define TM_AH  256u     // Ah: 96 cols
#define TM_AL  352u     // Al: 96 cols

#define NTHREADS 544    // 16 builder warps + 1 MMA warp
#define NROWS    6      // input rows per sub-band
#define NBANDS   2      // sub-bands per CTA (4 output rows each)

__global__ void __launch_bounds__(NTHREADS, 1)
conv_tc_kernel(const float* __restrict__ x,
               const float* __restrict__ base_b,
               float* __restrict__ y) {
#if HAS_TCGEN05
    extern __shared__ unsigned char sm[];
    __shared__ float sbb[COUT_];
    const uint32_t sbase = smem_u32(sm);
    uint32_t* scratch = (uint32_t*)(sm + SM_SCRATCH);

    const uint32_t tbase = (sbase + SCRATCH_END + 1023u) & ~1023u;
    unsigned char* tptr = sm + (tbase - sbase);

    const int tid = threadIdx.x;
    const int wid = tid >> 5;
    const int lid = tid & 31;
    const int h0 = blockIdx.x * 8;       // 8 output rows per CTA
    const int b  = blockIdx.y;
    const float* xb = x + ((size_t)b << 20);

    if (tid == 0) {
        MBAR_INIT(sbase + MB_MDONE, 1);
        MBAR_INIT(sbase + MB_AREADY, 1);
    }
    if (wid == 0) TC_ALLOC(sbase, 512);
    if (tid < COUT_) sbb[tid] = base_b[tid];
    if (tid < 64) { scratch[tid] = 0u; scratch[129 * 65 + tid] = 0u; }  // halo rows 0,129
    __syncthreads();
    uint32_t tmem;
    asm volatile("ld.shared.b32 %0, [%1];" : "=r"(tmem) : "r"(sbase));

    const uint64_t dB = make_desc(tbase + T_B);

    if (wid == 16) {
        // ================= MMA issue warp: 12 global rows =================
        for (int kg = 0; kg < NBANDS * NROWS; kg++) {
            const int ri = kg % NROWS;
            MBAR_WAIT(sbase + MB_AREADY, kg & 1);
            FENCE_ASYNC();
            TC_FENCE_AFTER();
            if (elect_one()) {
                int dylo = ri - 3 > 0 ? ri - 3 : 0;
                int dyhi = ri < 2 ? ri : 2;
                for (int dy = dylo; dy <= dyhi; dy++) {
                    int hh = ri - dy;                 // 0..3
                    uint32_t d = tmem + TM_D + hh * 64;
                    uint64_t bH = dB + (uint64_t)(dy * 3072);
                    uint64_t bL = bH + 1536;
#pragma unroll
                    for (int s = 0; s < 12; s++) {
                        uint64_t bo = (uint64_t)((s >> 2) * 512 + (s & 3) * 2);
                        mma_f16_ts(d, tmem + TM_AH + s * 8, bH + bo, IDESC_,
                                   !(dy == 0 && s == 0));
                    }
#pragma unroll
                    for (int s = 0; s < 12; s++) {
                        uint64_t bo = (uint64_t)((s >> 2) * 512 + (s & 3) * 2);
                        mma_f16_ts(d, tmem + TM_AL + s * 8, bH + bo, IDESC_, 1u);
                    }
#pragma unroll
                    for (int s = 0; s < 12; s++) {
                        uint64_t bo = (uint64_t)((s >> 2) * 512 + (s & 3) * 2);
                        mma_f16_ts(d, tmem + TM_AH + s * 8, bL + bo, IDESC_, 1u);
                    }
                }
                TC_COMMIT(sbase + MB_MDONE);
            }
        }
    } else {
        // ================= 16 builder warps =================
        // B prologue ONCE per CTA (3 dy x hi/lo, contiguous in g_wB)
        {
            const uint4* src = (const uint4*)(g_wB + (size_t)(b * 3) * 2 * 24576);
            uint4* dst = (uint4*)(tptr + T_B);
            for (int i = tid; i < (int)(T_SZ / 16); i += 512) dst[i] = src[i];
        }

        const int pf_w4 = tid & 31;
        const int ci_base = tid >> 5;        // ci = it*16 + ci_base (0..15)
        const int am = tid & 127;
        const int awg = tid >> 7;            // 0..3
        const uint32_t warp_off = (uint32_t)((tid & 127) >> 5) << 21;

        for (int band = 0; band < NBANDS; band++) {
            const int h0b = h0 + band * 4;

            float4 v[4];
            // load input row for ri=0 of this band (row = h0b-1; clamp)
            {
                int r = h0b - 1;
                bool valid = r >= 0;
                int rc = valid ? r : 0;
                const float4* xr4 = (const float4*)(xb + ((size_t)rc << 7));
#pragma unroll
                for (int it = 0; it < 4; it++) {
                    float4 t = xr4[((size_t)(it * 16 + ci_base) << 12) + pf_w4];
                    v[it] = valid ? t : make_float4(0.f, 0.f, 0.f, 0.f);
                }
            }

            for (int ri = 0; ri < NROWS; ri++) {
                const int kg = band * NROWS + ri;
                // stage scratch from registers
#pragma unroll
                for (int it = 0; it < 4; it++) {
                    float vv[4] = {v[it].x, v[it].y, v[it].z, v[it].w};
                    int ci = it * 16 + ci_base;
                    int wbase = (pf_w4 << 2) + 1;
#pragma unroll
                    for (int q = 0; q < 4; q++) {
                        __nv_bfloat16 hi = __float2bfloat16(vv[q]);
                        __nv_bfloat16 lo = __float2bfloat16(vv[q] - __bfloat162float(hi));
                        scratch[(wbase + q) * 65 + ci] =
                            (uint32_t)__bfloat16_as_ushort(hi) |
                            ((uint32_t)__bfloat16_as_ushort(lo) << 16);
                    }
                }
                BAR1_512();                  // scratch + (kg==0: B copy) visible

                // hoisted LDG: next input row within band
                if (ri + 1 < NROWS) {
                    int r = h0b + ri;
                    bool valid = r < H_;
                    int rc = valid ? r : (H_ - 1);
                    const float4* xr4 = (const float4*)(xb + ((size_t)rc << 7));
#pragma unroll
                    for (int it = 0; it < 4; it++) {
                        float4 t = xr4[((size_t)(it * 16 + ci_base) << 12) + pf_w4];
                        v[it] = valid ? t : make_float4(0.f, 0.f, 0.f, 0.f);
                    }
                }

                // wait prev global row's MMAs before overwriting A.
                // (band>0, ri==0: the inter-band epilogue already waited.)
                if (ri > 0) MBAR_WAIT(sbase + MB_MDONE, (kg - 1) & 1);

                // A build into TMEM (depends only on input row)
#pragma unroll
                for (int chunk = 0; chunk < 3; chunk++) {
                    int c0 = awg * 24 + chunk * 8;
                    uint32_t hi[8], lo[8];
#pragma unroll
                    for (int j = 0; j < 8; j++) {
                        int c = c0 + j;
                        int kk2 = 2 * c;
                        int dx = kk2 >> 6;
                        int ci = kk2 & 63;
                        const uint32_t* s2 = &scratch[(am + dx) * 65 + ci];
                        uint32_t w0 = s2[0], w1 = s2[1];
                        hi[j] = __byte_perm(w0, w1, 0x5410);
                        lo[j] = __byte_perm(w0, w1, 0x7632);
                    }
                    TC_ST_X8(tmem + TM_AH + c0 + warp_off, hi);
                    TC_ST_X8(tmem + TM_AL + c0 + warp_off, lo);
                }
                TC_WAIT_ST();
                TC_FENCE_BEFORE();
                BAR1_512();                  // all of A in TMEM
                if (tid == 0) MBAR_ARRIVE(sbase + MB_AREADY);
            }

            // band drain: last commit of this band has parity 1
            MBAR_WAIT(sbase + MB_MDONE, 1);
            TC_FENCE_AFTER();

            // epilogue: warp w: subpartition = w&3 (HW), hh = w>>2 (0..3)
            {
                int sub = wid & 3, hh = wid >> 2;
                int m = sub * 32 + lid;
                int h = h0b + hh;
                float* yr = y + ((size_t)b << 20) + ((size_t)h << 7) + m;
                uint32_t r0[32], r1[32];
                TC_LD_X32(r0, tmem + TM_D + hh * 64);
                TC_LD_X32(r1, tmem + TM_D + hh * 64 + 32);
                TC_WAIT_LD();
#pragma unroll
                for (int c = 0; c < 32; c++)
                    yr[(size_t)c << 14] = __uint_as_float(r0[c]) + sbb[c];
#pragma unroll
                for (int c = 0; c < 32; c++)
                    yr[(size_t)(c + 32) << 14] = __uint_as_float(r1[c]) + sbb[c + 32];
            }
            TC_FENCE_BEFORE();
            BAR1_512();                      // D fully read before next band reuses it
        }
    }

    __syncthreads();
    if (wid == 0) TC_DEALLOC(tmem, 512);

#else  // -------- generic-PTX fallback: correct scalar conv --------
    const int tid = threadIdx.x;
    const int h0 = blockIdx.x * 8;
    const int b  = blockIdx.y;
    const float* xb = x + ((size_t)b << 20);
    const float* wgt_b = g_wadapt + (size_t)b * KVOL_;
    for (int idx = tid; idx < 8 * 128 * 64; idx += NTHREADS) {
        int w = idx & 127;
        int rest = idx >> 7;
        int co = rest & 63;
        int hh = rest >> 6;
        int h = h0 + hh;
        float acc = base_b[co];
        const float* wgt = wgt_b + co * 576;
        for (int ci = 0; ci < CIN_; ci++) {
            const float* xp = xb + ((size_t)ci << 14);
            const float* wp = wgt + ci * 9;
            for (int ky = 0; ky < 3; ky++) {
                int ih = h + ky - 1;
                if ((unsigned)ih >= (unsigned)H_) continue;
                for (int kx = 0; kx < 3; kx++) {
                    int iw = w + kx - 1;
                    if ((unsigned)iw >= (unsigned)W_) continue;
                    acc += xp[(ih << 7) + iw] * wp[ky * 3 + kx];
                }
            }
        }
        y[((size_t)b << 20) + ((size_t)co << 14) + ((size_t)h << 7) + w] = acc;
    }
#endif
}

// ============================================================
extern "C" void kernel_launch(void* const* d_in, const int* in_sizes, int n_in,
                              void* d_out, int out_size) {
    const float* x      = (const float*)d_in[0];
    const float* base_w = (const float*)d_in[1];
    const float* base_b = (const float*)d_in[2];
    const float* w1     = (const float*)d_in[3];
    const float* b1     = (const float*)d_in[4];
    const float* w2     = (const float*)d_in[5];
    const float* b2     = (const float*)d_in[6];
    const float* scale  = (const float*)d_in[7];
    float* y = (float*)d_out;

    cudaFuncSetAttribute(conv_tc_kernel,
                         cudaFuncAttributeMaxDynamicSharedMemorySize, SM_TOTAL);

    pool_kernel<<<B_ * CIN_, 256>>>(x);
    mlp1_kernel<<<B_, 64>>>(w1, b1);
    adapt_kernel<<<KVOL_ / 32, 256>>>(base_w, w2, b2, scale);
    conv_tc_kernel<<<dim3(H_ / 8, B_), NTHREADS, SM_TOTAL>>>(x, base_b, y);
}